// round 1
// baseline (speedup 1.0000x reference)
#include <cuda_runtime.h>
#include <math.h>

#define B_   1024
#define T_   100
#define XD_  38
#define H_   500
#define ZD_  16
#define L_   3
#define G3H  (3*H_)   // 1500

// ----------------------------- scratch (static, no allocation) --------------
__device__ float g_hq0[B_*H_];
__device__ float g_hq1[B_*H_];
__device__ float g_hp0[B_*H_];
__device__ float g_hp1[B_*H_];
__device__ float g_Gh[B_*G3H];
__device__ float g_WhhTq[H_*G3H];
__device__ float g_WhhTp[H_*G3H];
__device__ float g_WihTq[XD_*G3H];
__device__ float g_WihTp[ZD_*G3H];
__device__ float g_uhat[L_*ZD_];
__device__ float g_zzero[B_*ZD_];

// ----------------------------- math helpers ---------------------------------
__device__ __forceinline__ float sigmoidf_(float x){ return 1.0f/(1.0f+expf(-x)); }
__device__ __forceinline__ float softplusf_(float x){ return (x>20.0f)? x : log1pf(expf(x)); }

// ----------------------------- init ------------------------------------------
__global__ void init_kernel(float* __restrict__ out_ld){
    int i = blockIdx.x*blockDim.x + threadIdx.x;
    int stride = gridDim.x*blockDim.x;
    for (int k=i; k<B_*H_; k+=stride){ g_hq0[k]=0.f; g_hp0[k]=0.f; }
    for (int k=i; k<B_*ZD_; k+=stride) g_zzero[k]=0.f;
    for (int k=i; k<B_;     k+=stride) out_ld[k]=0.f;
}

// ----------------------------- transpose W[R,C] -> WT[C,R] ------------------
__global__ void transpose_kernel(const float* __restrict__ W, float* __restrict__ WT,
                                 int R, int C){
    int idx = blockIdx.x*blockDim.x + threadIdx.x;
    if (idx < R*C){
        int r = idx / C, c = idx - r*C;
        WT[(size_t)c*R + r] = W[idx];
    }
}

// ----------------------------- planar-flow u_hat ----------------------------
__global__ void uhat_kernel(const float* __restrict__ fu, const float* __restrict__ fw){
    int k = threadIdx.x;
    if (k < L_){
        float wu=0.f, ww=0.f;
        for (int j=0;j<ZD_;j++){ wu += fw[k*ZD_+j]*fu[k*ZD_+j]; ww += fw[k*ZD_+j]*fw[k*ZD_+j]; }
        float m = -1.0f + softplusf_(wu);
        float scale = (m - wu)/(ww + 1e-6f);
        for (int j=0;j<ZD_;j++) g_uhat[k*ZD_+j] = fu[k*ZD_+j] + scale*fw[k*ZD_+j];
    }
}

// ----------------------------- SGEMM C = A[M,K] * B[K,N] + bias[N] ----------
#define BM 128
#define BN 64
#define BKK 8
#define TM 8
#define TN 4
__global__ __launch_bounds__(256)
void sgemm_bias(const float* __restrict__ A, const float* __restrict__ B,
                const float* __restrict__ bias, float* __restrict__ C,
                int M, int N, int K){
    __shared__ __align__(16) float As[BKK][BM];
    __shared__ __align__(16) float Bs[BKK][BN];
    int tid = threadIdx.x;
    int m0 = blockIdx.y*BM, n0 = blockIdx.x*BN;
    int ty = tid >> 4, tx = tid & 15;

    float acc[TM][TN];
#pragma unroll
    for (int i=0;i<TM;i++)
#pragma unroll
        for (int j=0;j<TN;j++) acc[i][j]=0.f;

    int am  = tid >> 1;            // 0..127
    int ak0 = (tid & 1) * 4;       // 0 or 4
    int bk  = tid >> 5;            // 0..7
    int bn0 = (tid & 31) * 2;      // 0..62

    for (int k0=0; k0<K; k0+=BKK){
#pragma unroll
        for (int jj=0;jj<4;jj++){
            int k = ak0 + jj;
            float v = 0.f;
            if (k0+k < K && m0+am < M) v = A[(size_t)(m0+am)*K + k0 + k];
            As[k][am] = v;
        }
#pragma unroll
        for (int jj=0;jj<2;jj++){
            int n = bn0 + jj;
            float v = 0.f;
            if (k0+bk < K && n0+n < N) v = B[(size_t)(k0+bk)*N + n0 + n];
            Bs[bk][n] = v;
        }
        __syncthreads();
#pragma unroll
        for (int kk=0; kk<BKK; kk++){
            float4 a0 = *reinterpret_cast<const float4*>(&As[kk][ty*TM]);
            float4 a1 = *reinterpret_cast<const float4*>(&As[kk][ty*TM+4]);
            float4 bv = *reinterpret_cast<const float4*>(&Bs[kk][tx*TN]);
            float a[TM] = {a0.x,a0.y,a0.z,a0.w,a1.x,a1.y,a1.z,a1.w};
            float bb[TN] = {bv.x,bv.y,bv.z,bv.w};
#pragma unroll
            for (int i=0;i<TM;i++)
#pragma unroll
                for (int j=0;j<TN;j++)
                    acc[i][j] = fmaf(a[i], bb[j], acc[i][j]);
        }
        __syncthreads();
    }
#pragma unroll
    for (int i=0;i<TM;i++){
        int m = m0 + ty*TM + i;
        if (m >= M) continue;
#pragma unroll
        for (int j=0;j<TN;j++){
            int n = n0 + tx*TN + j;
            if (n < N) C[(size_t)m*N + n] = acc[i][j] + bias[n];
        }
    }
}

// ----------------------------- GRU combine ----------------------------------
// h_new = (1-z)*n + z*h_prev with gates from inline x-projection + precomputed Gh
#define NB 8
__global__ __launch_bounds__(128)
void gru_combine(const float* __restrict__ xbase, int xstride, int XIN,
                 const float* __restrict__ WihT, const float* __restrict__ bih,
                 const float* __restrict__ Gh,
                 const float* __restrict__ h_prev, float* __restrict__ h_new){
    __shared__ float xs[NB][40];
    int b0 = blockIdx.y * NB;
    int j  = blockIdx.x*blockDim.x + threadIdx.x;
    for (int idx=threadIdx.x; idx<NB*XIN; idx+=blockDim.x){
        int r = idx / XIN, d = idx - r*XIN;
        xs[r][d] = xbase[(size_t)(b0+r)*xstride + d];
    }
    __syncthreads();
    if (j >= H_) return;

    float ar[NB], az[NB], an[NB];
#pragma unroll
    for (int r=0;r<NB;r++){ ar[r]=0.f; az[r]=0.f; an[r]=0.f; }
    for (int d=0; d<XIN; d++){
        const float* wrow = WihT + (size_t)d*G3H;
        float w0 = wrow[j], w1 = wrow[H_+j], w2 = wrow[2*H_+j];
#pragma unroll
        for (int r=0;r<NB;r++){
            float xv = xs[r][d];
            ar[r] = fmaf(xv, w0, ar[r]);
            az[r] = fmaf(xv, w1, az[r]);
            an[r] = fmaf(xv, w2, an[r]);
        }
    }
    float bR = bih[j], bZ = bih[H_+j], bN = bih[2*H_+j];
#pragma unroll
    for (int r=0;r<NB;r++){
        const float* gh = Gh + (size_t)(b0+r)*G3H;
        float rr = sigmoidf_(ar[r] + bR + gh[j]);
        float zz = sigmoidf_(az[r] + bZ + gh[H_+j]);
        float nn = tanhf    (an[r] + bN + rr*gh[2*H_+j]);
        size_t hi = (size_t)(b0+r)*H_ + j;
        h_new[hi] = (1.f - zz)*nn + zz*h_prev[hi];
    }
}

// ----------------------------- z step (mu/std + planar flows) ---------------
__global__ __launch_bounds__(32)
void zstep_kernel(const float* __restrict__ h_t,
                  const float* __restrict__ eps,
                  const float* __restrict__ zprev, int zstride,
                  const float* __restrict__ Wqm, const float* __restrict__ bqm,
                  const float* __restrict__ Wqs, const float* __restrict__ bqs,
                  const float* __restrict__ fw, const float* __restrict__ fb,
                  float* __restrict__ out_z, float* __restrict__ out_mu,
                  float* __restrict__ out_std, float* __restrict__ out_ld, int t){
    __shared__ float comb[H_+ZD_];
    __shared__ float smu[ZD_], sstd[ZD_], zsh[ZD_];
    int b = blockIdx.x, lane = threadIdx.x;
    for (int i=lane; i<H_; i+=32) comb[i] = h_t[(size_t)b*H_ + i];
    if (lane < ZD_) comb[H_+lane] = zprev[(size_t)b*zstride + lane];
    __syncwarp();

    int j = lane & 15;
    const float* W = (lane < 16 ? Wqm : Wqs) + (size_t)j*(H_+ZD_);
    float acc = 0.f;
    for (int i=0;i<H_+ZD_;i++) acc = fmaf(comb[i], W[i], acc);
    size_t oidx = ((size_t)b*T_ + t)*ZD_ + j;
    if (lane < 16){ float mu = acc + bqm[j]; smu[j] = mu; out_mu[oidx] = mu; }
    else          { float s  = softplusf_(acc + bqs[j]) + 1e-4f; sstd[j] = s; out_std[oidx] = s; }
    __syncwarp();

    if (lane < ZD_)
        zsh[lane] = smu[lane] + eps[((size_t)b*T_ + t)*ZD_ + lane]*sstd[lane];
    __syncwarp();

    if (lane == 0){
        float ld = 0.f;
#pragma unroll
        for (int k=0;k<L_;k++){
            float dot = 0.f;
            for (int i=0;i<ZD_;i++) dot = fmaf(zsh[i], fw[k*ZD_+i], dot);
            float hh = tanhf(dot + fb[k]);
            float psiu = 0.f;
            for (int i=0;i<ZD_;i++){
                zsh[i] += g_uhat[k*ZD_+i]*hh;
                psiu = fmaf((1.f - hh*hh)*fw[k*ZD_+i], g_uhat[k*ZD_+i], psiu);
            }
            ld += logf(fabsf(1.f + psiu) + 1e-6f);
        }
        out_ld[b] += ld;
    }
    __syncwarp();
    if (lane < ZD_) out_z[((size_t)b*T_ + t)*ZD_ + lane] = zsh[lane];
}

// ----------------------------- reconstruction head --------------------------
__global__ __launch_bounds__(128)
void recon_kernel(const float* __restrict__ h_p,
                  const float* __restrict__ Wpm, const float* __restrict__ bpm,
                  const float* __restrict__ Wps, const float* __restrict__ bps,
                  float* __restrict__ out_mu, float* __restrict__ out_std, int t){
    __shared__ float hs[H_];
    int b = blockIdx.x;
    for (int i=threadIdx.x; i<H_; i+=blockDim.x) hs[i] = h_p[(size_t)b*H_ + i];
    __syncthreads();
    int tid = threadIdx.x;
    if (tid < XD_){
        const float* w = Wpm + (size_t)tid*H_;
        float acc = 0.f;
        for (int i=0;i<H_;i++) acc = fmaf(hs[i], w[i], acc);
        out_mu[((size_t)b*T_ + t)*XD_ + tid] = acc + bpm[tid];
    } else if (tid >= 64 && tid < 64+XD_){
        int d = tid - 64;
        const float* w = Wps + (size_t)d*H_;
        float acc = 0.f;
        for (int i=0;i<H_;i++) acc = fmaf(hs[i], w[i], acc);
        out_std[((size_t)b*T_ + t)*XD_ + d] = softplusf_(acc + bps[d]) + 1e-4f;
    }
}

// ----------------------------- launcher --------------------------------------
extern "C" void kernel_launch(void* const* d_in, const int* in_sizes, int n_in,
                              void* d_out, int out_size){
    const float* x     = (const float*)d_in[0];
    const float* eps   = (const float*)d_in[1];
    const float* Wih_q = (const float*)d_in[2];
    const float* Whh_q = (const float*)d_in[3];
    const float* bih_q = (const float*)d_in[4];
    const float* bhh_q = (const float*)d_in[5];
    const float* Wqm   = (const float*)d_in[6];
    const float* bqm   = (const float*)d_in[7];
    const float* Wqs   = (const float*)d_in[8];
    const float* bqs   = (const float*)d_in[9];
    const float* Wih_p = (const float*)d_in[10];
    const float* Whh_p = (const float*)d_in[11];
    const float* bih_p = (const float*)d_in[12];
    const float* bhh_p = (const float*)d_in[13];
    const float* Wpm   = (const float*)d_in[14];
    const float* bpm   = (const float*)d_in[15];
    const float* Wps   = (const float*)d_in[16];
    const float* bps   = (const float*)d_in[17];
    const float* fu    = (const float*)d_in[18];
    const float* fw    = (const float*)d_in[19];
    const float* fb    = (const float*)d_in[20];

    float* out = (float*)d_out;
    float* out_rm  = out;                                   // [B,T,XD]
    float* out_rs  = out_rm  + (size_t)B_*T_*XD_;           // [B,T,XD]
    float* out_z   = out_rs  + (size_t)B_*T_*XD_;           // [B,T,ZD]
    float* out_mu  = out_z   + (size_t)B_*T_*ZD_;           // [B,T,ZD]
    float* out_std = out_mu  + (size_t)B_*T_*ZD_;           // [B,T,ZD]
    float* out_ld  = out_std + (size_t)B_*T_*ZD_;           // [B,1]

    float *hq0,*hq1,*hp0,*hp1,*Gh,*WhhTq,*WhhTp,*WihTq,*WihTp,*zzero;
    cudaGetSymbolAddress((void**)&hq0,   g_hq0);
    cudaGetSymbolAddress((void**)&hq1,   g_hq1);
    cudaGetSymbolAddress((void**)&hp0,   g_hp0);
    cudaGetSymbolAddress((void**)&hp1,   g_hp1);
    cudaGetSymbolAddress((void**)&Gh,    g_Gh);
    cudaGetSymbolAddress((void**)&WhhTq, g_WhhTq);
    cudaGetSymbolAddress((void**)&WhhTp, g_WhhTp);
    cudaGetSymbolAddress((void**)&WihTq, g_WihTq);
    cudaGetSymbolAddress((void**)&WihTp, g_WihTp);
    cudaGetSymbolAddress((void**)&zzero, g_zzero);

    init_kernel<<<512,256>>>(out_ld);
    {
        int n = G3H*H_;
        transpose_kernel<<<(n+255)/256,256>>>(Whh_q, WhhTq, G3H, H_);
        transpose_kernel<<<(n+255)/256,256>>>(Whh_p, WhhTp, G3H, H_);
        int nq = G3H*XD_;
        transpose_kernel<<<(nq+255)/256,256>>>(Wih_q, WihTq, G3H, XD_);
        int np = G3H*ZD_;
        transpose_kernel<<<(np+255)/256,256>>>(Wih_p, WihTp, G3H, ZD_);
    }
    uhat_kernel<<<1,32>>>(fu, fw);

    dim3 gemm_grid((G3H+BN-1)/BN, (B_+BM-1)/BM);
    dim3 comb_grid((H_+127)/128, B_/NB);

    float* hq[2] = {hq0, hq1};
    float* hp[2] = {hp0, hp1};
    int cq = 0, cp = 0;

    for (int t=0; t<T_; t++){
        // ---- q GRU step ----
        sgemm_bias<<<gemm_grid,256>>>(hq[cq], WhhTq, bhh_q, Gh, B_, G3H, H_);
        gru_combine<<<comb_grid,128>>>(x + (size_t)t*XD_, T_*XD_, XD_,
                                       WihTq, bih_q, Gh, hq[cq], hq[cq^1]);
        cq ^= 1;

        // ---- variational z step + planar flows ----
        const float* zprev = (t==0) ? zzero : (out_z + (size_t)(t-1)*ZD_);
        int zstride = (t==0) ? ZD_ : T_*ZD_;
        zstep_kernel<<<B_,32>>>(hq[cq], eps, zprev, zstride,
                                Wqm, bqm, Wqs, bqs, fw, fb,
                                out_z, out_mu, out_std, out_ld, t);

        // ---- p GRU step (input = z_seq[:,t]) ----
        sgemm_bias<<<gemm_grid,256>>>(hp[cp], WhhTp, bhh_p, Gh, B_, G3H, H_);
        gru_combine<<<comb_grid,128>>>(out_z + (size_t)t*ZD_, T_*ZD_, ZD_,
                                       WihTp, bih_p, Gh, hp[cp], hp[cp^1]);
        cp ^= 1;

        // ---- reconstruction heads ----
        recon_kernel<<<B_,128>>>(hp[cp], Wpm, bpm, Wps, bps, out_rm, out_rs, t);
    }
}

// round 2
// speedup vs baseline: 1.5230x; 1.5230x over previous
#include <cuda_runtime.h>
#include <math.h>

#define B_   1024
#define T_   100
#define XD_  38
#define H_   500
#define ZD_  16
#define L_   3
#define G3H  1500
#define KP   512     // padded K (H_ -> 512)
#define NP   1536    // padded N (3H -> 1536)
#define M2   2048    // hq (1024) + hp (1024) stacked
#define NB   8

// ----------------------------- scratch (static, no allocation) --------------
__device__ float g_h_all[M2*KP];      // rows 0..1023 = hq, 1024..2047 = hp  (K padded w/ zeros)
__device__ float g_Gh[M2*NP];         // recurrent gate pre-activations
__device__ float g_WhhTq[KP*NP];      // padded transpose of Whh_q
__device__ float g_WhhTp[KP*NP];
__device__ float g_WihTq[XD_*G3H];
__device__ float g_WihTp[ZD_*G3H];
__device__ float g_uhat[L_*ZD_];
__device__ float g_zzero[B_*ZD_];

// ----------------------------- math helpers ---------------------------------
__device__ __forceinline__ float sigmoidf_(float x){ return 1.0f/(1.0f+expf(-x)); }
__device__ __forceinline__ float softplusf_(float x){ return (x>20.0f)? x : log1pf(expf(x)); }

// ----------------------------- init ------------------------------------------
__global__ void init_kernel(float* __restrict__ out_ld){
    int i = blockIdx.x*blockDim.x + threadIdx.x;
    int stride = gridDim.x*blockDim.x;
    for (int k=i; k<M2*KP;  k+=stride) g_h_all[k]=0.f;
    for (int k=i; k<KP*NP;  k+=stride){ g_WhhTq[k]=0.f; g_WhhTp[k]=0.f; }
    for (int k=i; k<B_*ZD_; k+=stride) g_zzero[k]=0.f;
    for (int k=i; k<B_;     k+=stride) out_ld[k]=0.f;
}

// ----------------------------- transposes ------------------------------------
__global__ void transpose_whh(const float* __restrict__ W, float* __restrict__ WT){
    int idx = blockIdx.x*blockDim.x + threadIdx.x;
    if (idx < G3H*H_){
        int g = idx / H_, k = idx - g*H_;
        WT[(size_t)k*NP + g] = W[idx];
    }
}
__global__ void transpose_wih(const float* __restrict__ W, float* __restrict__ WT, int C){
    int idx = blockIdx.x*blockDim.x + threadIdx.x;
    if (idx < G3H*C){
        int g = idx / C, d = idx - g*C;
        WT[(size_t)d*G3H + g] = W[idx];
    }
}

// ----------------------------- planar-flow u_hat ----------------------------
__global__ void uhat_kernel(const float* __restrict__ fu, const float* __restrict__ fw){
    int k = threadIdx.x;
    if (k < L_){
        float wu=0.f, ww=0.f;
        for (int j=0;j<ZD_;j++){ wu += fw[k*ZD_+j]*fu[k*ZD_+j]; ww += fw[k*ZD_+j]*fw[k*ZD_+j]; }
        float m = -1.0f + softplusf_(wu);
        float scale = (m - wu)/(ww + 1e-6f);
        for (int j=0;j<ZD_;j++) g_uhat[k*ZD_+j] = fu[k*ZD_+j] + scale*fw[k*ZD_+j];
    }
}

// ----------------------------- combined recurrent GEMM -----------------------
// C[m][n] = sum_k A[m][k]*B[k][n] + bias[n], B/bias selected per M-half.
// A: [M2][KP], B: [KP][NP], C: [M2][NP]. 128x64 tile, 8x8/thread, 128 threads.
__global__ __launch_bounds__(128)
void gemm_all(const float* __restrict__ A,
              const float* __restrict__ Bq, const float* __restrict__ Bp,
              const float* __restrict__ biasq, const float* __restrict__ biasp,
              float* __restrict__ C)
{
    __shared__ __align__(16) float As[16][128];
    __shared__ __align__(16) float Bs[16][64];

    int tid = threadIdx.x;
    int m0 = blockIdx.y * 128;
    int n0 = blockIdx.x * 64;
    const float* Bsel = (m0 < 1024) ? Bq : Bp;
    const float* bias = (m0 < 1024) ? biasq : biasp;

    int a_row = tid >> 2;        // 0..31
    int a_c4  = tid & 3;         // 0..3  (k float4)
    int b_row = tid >> 3;        // 0..15 (k)
    int b_c4  = tid & 7;         // 0..7  (n float4)

    int ty = tid >> 3;           // 0..15 -> rows ty*8..ty*8+7
    int tx = tid & 7;            // 0..7  -> cols tx*8..tx*8+7

    float4 pa[4];
    float4 pb[2];

#pragma unroll
    for (int it=0; it<4; it++)
        pa[it] = *reinterpret_cast<const float4*>(&A[(size_t)(m0 + a_row + 32*it)*KP + a_c4*4]);
#pragma unroll
    for (int it=0; it<2; it++)
        pb[it] = *reinterpret_cast<const float4*>(&Bsel[(size_t)b_row*NP + n0 + (b_c4 + 8*it)*4]);

    float acc[8][8];
#pragma unroll
    for (int i=0;i<8;i++)
#pragma unroll
        for (int j=0;j<8;j++) acc[i][j]=0.f;

    for (int k0 = 0; k0 < KP; k0 += 16){
#pragma unroll
        for (int it=0; it<4; it++){
            As[a_c4*4+0][a_row+32*it] = pa[it].x;
            As[a_c4*4+1][a_row+32*it] = pa[it].y;
            As[a_c4*4+2][a_row+32*it] = pa[it].z;
            As[a_c4*4+3][a_row+32*it] = pa[it].w;
        }
#pragma unroll
        for (int it=0; it<2; it++)
            *reinterpret_cast<float4*>(&Bs[b_row][(b_c4+8*it)*4]) = pb[it];
        __syncthreads();

        int k1 = k0 + 16;
        if (k1 < KP){
#pragma unroll
            for (int it=0; it<4; it++)
                pa[it] = *reinterpret_cast<const float4*>(&A[(size_t)(m0 + a_row + 32*it)*KP + k1 + a_c4*4]);
#pragma unroll
            for (int it=0; it<2; it++)
                pb[it] = *reinterpret_cast<const float4*>(&Bsel[(size_t)(k1 + b_row)*NP + n0 + (b_c4+8*it)*4]);
        }

#pragma unroll
        for (int kk=0; kk<16; kk++){
            float4 a0 = *reinterpret_cast<const float4*>(&As[kk][ty*8]);
            float4 a1 = *reinterpret_cast<const float4*>(&As[kk][ty*8+4]);
            float4 b0 = *reinterpret_cast<const float4*>(&Bs[kk][tx*8]);
            float4 b1 = *reinterpret_cast<const float4*>(&Bs[kk][tx*8+4]);
            float av[8] = {a0.x,a0.y,a0.z,a0.w,a1.x,a1.y,a1.z,a1.w};
            float bv[8] = {b0.x,b0.y,b0.z,b0.w,b1.x,b1.y,b1.z,b1.w};
#pragma unroll
            for (int i=0;i<8;i++)
#pragma unroll
                for (int j=0;j<8;j++)
                    acc[i][j] = fmaf(av[i], bv[j], acc[i][j]);
        }
        __syncthreads();
    }

#pragma unroll
    for (int i=0;i<8;i++){
        int m = m0 + ty*8 + i;
#pragma unroll
        for (int j=0;j<8;j++){
            int n = n0 + tx*8 + j;
            if (n < G3H) C[(size_t)m*NP + n] = acc[i][j] + bias[n];
        }
    }
}

// ----------------------------- q GRU combine ---------------------------------
__global__ __launch_bounds__(128)
void q_combine(const float* __restrict__ xbase,
               const float* __restrict__ WihT, const float* __restrict__ bih,
               const float* __restrict__ Gh,
               float* __restrict__ h_all){
    __shared__ float xs[NB][XD_+2];
    int b0 = blockIdx.y * NB;
    int j  = blockIdx.x*blockDim.x + threadIdx.x;
    for (int idx=threadIdx.x; idx<NB*XD_; idx+=blockDim.x){
        int r = idx / XD_, d = idx - r*XD_;
        xs[r][d] = xbase[(size_t)(b0+r)*(T_*XD_) + d];
    }
    __syncthreads();
    if (j >= H_) return;

    float ar[NB], az[NB], an[NB];
#pragma unroll
    for (int r=0;r<NB;r++){ ar[r]=0.f; az[r]=0.f; an[r]=0.f; }
    for (int d=0; d<XD_; d++){
        const float* wrow = WihT + (size_t)d*G3H;
        float w0 = wrow[j], w1 = wrow[H_+j], w2 = wrow[2*H_+j];
#pragma unroll
        for (int r=0;r<NB;r++){
            float xv = xs[r][d];
            ar[r] = fmaf(xv, w0, ar[r]);
            az[r] = fmaf(xv, w1, az[r]);
            an[r] = fmaf(xv, w2, an[r]);
        }
    }
    float bR = bih[j], bZ = bih[H_+j], bN = bih[2*H_+j];
#pragma unroll
    for (int r=0;r<NB;r++){
        const float* gh = Gh + (size_t)(b0+r)*NP;
        float rr = sigmoidf_(ar[r] + bR + gh[j]);
        float zz = sigmoidf_(az[r] + bZ + gh[H_+j]);
        float nn = tanhf    (an[r] + bN + rr*gh[2*H_+j]);
        size_t hi = (size_t)(b0+r)*KP + j;
        h_all[hi] = (1.f - zz)*nn + zz*h_all[hi];
    }
}

// ----------------------------- z step (mu/std + planar flows) ----------------
__global__ __launch_bounds__(32)
void zstep_kernel(const float* __restrict__ h_all,
                  const float* __restrict__ eps,
                  const float* __restrict__ zprev, int zstride,
                  const float* __restrict__ Wqm, const float* __restrict__ bqm,
                  const float* __restrict__ Wqs, const float* __restrict__ bqs,
                  const float* __restrict__ fw, const float* __restrict__ fb,
                  float* __restrict__ out_z, float* __restrict__ out_mu,
                  float* __restrict__ out_std, float* __restrict__ out_ld, int t){
    __shared__ float comb[H_+ZD_];
    __shared__ float smu[ZD_], sstd[ZD_], zsh[ZD_];
    int b = blockIdx.x, lane = threadIdx.x;
    for (int i=lane; i<H_; i+=32) comb[i] = h_all[(size_t)b*KP + i];
    if (lane < ZD_) comb[H_+lane] = zprev[(size_t)b*zstride + lane];
    __syncwarp();

    int j = lane & 15;
    const float* W = (lane < 16 ? Wqm : Wqs) + (size_t)j*(H_+ZD_);
    float acc = 0.f;
    for (int i=0;i<H_+ZD_;i++) acc = fmaf(comb[i], W[i], acc);
    size_t oidx = ((size_t)b*T_ + t)*ZD_ + j;
    if (lane < 16){ float mu = acc + bqm[j]; smu[j] = mu; out_mu[oidx] = mu; }
    else          { float s  = softplusf_(acc + bqs[j]) + 1e-4f; sstd[j] = s; out_std[oidx] = s; }
    __syncwarp();

    if (lane < ZD_)
        zsh[lane] = smu[lane] + eps[((size_t)b*T_ + t)*ZD_ + lane]*sstd[lane];
    __syncwarp();

    if (lane == 0){
        float ld = 0.f;
#pragma unroll
        for (int k=0;k<L_;k++){
            float dot = 0.f;
            for (int i=0;i<ZD_;i++) dot = fmaf(zsh[i], fw[k*ZD_+i], dot);
            float hh = tanhf(dot + fb[k]);
            float psiu = 0.f;
            for (int i=0;i<ZD_;i++){
                zsh[i] += g_uhat[k*ZD_+i]*hh;
                psiu = fmaf((1.f - hh*hh)*fw[k*ZD_+i], g_uhat[k*ZD_+i], psiu);
            }
            ld += logf(fabsf(1.f + psiu) + 1e-6f);
        }
        out_ld[b] += ld;
    }
    __syncwarp();
    if (lane < ZD_) out_z[((size_t)b*T_ + t)*ZD_ + lane] = zsh[lane];
}

// ----------------------------- p GRU combine + reconstruction ----------------
__global__ __launch_bounds__(256)
void p_fused(const float* __restrict__ z_t,
             const float* __restrict__ WihT, const float* __restrict__ bih,
             const float* __restrict__ Gh,
             float* __restrict__ h_all,
             const float* __restrict__ Wpm, const float* __restrict__ bpm,
             const float* __restrict__ Wps, const float* __restrict__ bps,
             float* __restrict__ out_mu, float* __restrict__ out_std, int t){
    __shared__ float zs[NB][ZD_];
    __shared__ float hs[NB][H_];
    int b0 = blockIdx.x * NB;
    int tid = threadIdx.x;
    if (tid < NB*ZD_){
        int r = tid >> 4, d = tid & 15;
        zs[r][d] = z_t[(size_t)(b0+r)*(T_*ZD_) + d];
    }
    __syncthreads();

    // phase 1: p-GRU combine (writes hp into smem + global for next step GEMM)
    for (int j = tid; j < H_; j += 256){
        float ar[NB], az[NB], an[NB];
#pragma unroll
        for (int r=0;r<NB;r++){ ar[r]=0.f; az[r]=0.f; an[r]=0.f; }
#pragma unroll
        for (int d=0; d<ZD_; d++){
            const float* wrow = WihT + (size_t)d*G3H;
            float w0 = wrow[j], w1 = wrow[H_+j], w2 = wrow[2*H_+j];
#pragma unroll
            for (int r=0;r<NB;r++){
                float zv = zs[r][d];
                ar[r] = fmaf(zv, w0, ar[r]);
                az[r] = fmaf(zv, w1, az[r]);
                an[r] = fmaf(zv, w2, an[r]);
            }
        }
        float bR = bih[j], bZ = bih[H_+j], bN = bih[2*H_+j];
#pragma unroll
        for (int r=0;r<NB;r++){
            const float* gh = Gh + (size_t)(1024 + b0 + r)*NP;
            float rr = sigmoidf_(ar[r] + bR + gh[j]);
            float zz = sigmoidf_(az[r] + bZ + gh[H_+j]);
            float nn = tanhf    (an[r] + bN + rr*gh[2*H_+j]);
            size_t hi = (size_t)(1024 + b0 + r)*KP + j;
            float hv = (1.f - zz)*nn + zz*h_all[hi];
            h_all[hi] = hv;
            hs[r][j]  = hv;
        }
    }
    __syncthreads();

    // phase 2: reconstruction heads (hp read from smem)
    int rg = tid >> 7;      // 0/1 -> rows rg*4..rg*4+3
    int o  = tid & 127;
    if (o < XD_){
        const float* w = Wpm + (size_t)o*H_;
        float a0=0.f,a1=0.f,a2=0.f,a3=0.f;
        for (int i=0;i<H_;i++){
            float wv = w[i];
            a0 = fmaf(hs[rg*4+0][i], wv, a0);
            a1 = fmaf(hs[rg*4+1][i], wv, a1);
            a2 = fmaf(hs[rg*4+2][i], wv, a2);
            a3 = fmaf(hs[rg*4+3][i], wv, a3);
        }
        float bb = bpm[o];
        out_mu[((size_t)(b0+rg*4+0)*T_+t)*XD_+o] = a0+bb;
        out_mu[((size_t)(b0+rg*4+1)*T_+t)*XD_+o] = a1+bb;
        out_mu[((size_t)(b0+rg*4+2)*T_+t)*XD_+o] = a2+bb;
        out_mu[((size_t)(b0+rg*4+3)*T_+t)*XD_+o] = a3+bb;
    } else if (o >= 64 && o < 64+XD_){
        int d = o - 64;
        const float* w = Wps + (size_t)d*H_;
        float a0=0.f,a1=0.f,a2=0.f,a3=0.f;
        for (int i=0;i<H_;i++){
            float wv = w[i];
            a0 = fmaf(hs[rg*4+0][i], wv, a0);
            a1 = fmaf(hs[rg*4+1][i], wv, a1);
            a2 = fmaf(hs[rg*4+2][i], wv, a2);
            a3 = fmaf(hs[rg*4+3][i], wv, a3);
        }
        float bb = bps[d];
        out_std[((size_t)(b0+rg*4+0)*T_+t)*XD_+d] = softplusf_(a0+bb)+1e-4f;
        out_std[((size_t)(b0+rg*4+1)*T_+t)*XD_+d] = softplusf_(a1+bb)+1e-4f;
        out_std[((size_t)(b0+rg*4+2)*T_+t)*XD_+d] = softplusf_(a2+bb)+1e-4f;
        out_std[((size_t)(b0+rg*4+3)*T_+t)*XD_+d] = softplusf_(a3+bb)+1e-4f;
    }
}

// ----------------------------- launcher --------------------------------------
extern "C" void kernel_launch(void* const* d_in, const int* in_sizes, int n_in,
                              void* d_out, int out_size){
    const float* x     = (const float*)d_in[0];
    const float* eps   = (const float*)d_in[1];
    const float* Wih_q = (const float*)d_in[2];
    const float* Whh_q = (const float*)d_in[3];
    const float* bih_q = (const float*)d_in[4];
    const float* bhh_q = (const float*)d_in[5];
    const float* Wqm   = (const float*)d_in[6];
    const float* bqm   = (const float*)d_in[7];
    const float* Wqs   = (const float*)d_in[8];
    const float* bqs   = (const float*)d_in[9];
    const float* Wih_p = (const float*)d_in[10];
    const float* Whh_p = (const float*)d_in[11];
    const float* bih_p = (const float*)d_in[12];
    const float* bhh_p = (const float*)d_in[13];
    const float* Wpm   = (const float*)d_in[14];
    const float* bpm   = (const float*)d_in[15];
    const float* Wps   = (const float*)d_in[16];
    const float* bps   = (const float*)d_in[17];
    const float* fu    = (const float*)d_in[18];
    const float* fw    = (const float*)d_in[19];
    const float* fb    = (const float*)d_in[20];

    float* out = (float*)d_out;
    float* out_rm  = out;                                   // [B,T,XD]
    float* out_rs  = out_rm  + (size_t)B_*T_*XD_;           // [B,T,XD]
    float* out_z   = out_rs  + (size_t)B_*T_*XD_;           // [B,T,ZD]
    float* out_mu  = out_z   + (size_t)B_*T_*ZD_;           // [B,T,ZD]
    float* out_std = out_mu  + (size_t)B_*T_*ZD_;           // [B,T,ZD]
    float* out_ld  = out_std + (size_t)B_*T_*ZD_;           // [B,1]

    float *h_all,*Gh,*WhhTq,*WhhTp,*WihTq,*WihTp,*zzero;
    cudaGetSymbolAddress((void**)&h_all, g_h_all);
    cudaGetSymbolAddress((void**)&Gh,    g_Gh);
    cudaGetSymbolAddress((void**)&WhhTq, g_WhhTq);
    cudaGetSymbolAddress((void**)&WhhTp, g_WhhTp);
    cudaGetSymbolAddress((void**)&WihTq, g_WihTq);
    cudaGetSymbolAddress((void**)&WihTp, g_WihTp);
    cudaGetSymbolAddress((void**)&zzero, g_zzero);

    init_kernel<<<1024,256>>>(out_ld);
    {
        int n = G3H*H_;
        transpose_whh<<<(n+255)/256,256>>>(Whh_q, WhhTq);
        transpose_whh<<<(n+255)/256,256>>>(Whh_p, WhhTp);
        int nq = G3H*XD_;
        transpose_wih<<<(nq+255)/256,256>>>(Wih_q, WihTq, XD_);
        int np = G3H*ZD_;
        transpose_wih<<<(np+255)/256,256>>>(Wih_p, WihTp, ZD_);
    }
    uhat_kernel<<<1,32>>>(fu, fw);

    dim3 gemm_grid(NP/64, M2/128);          // 24 x 16 = 384 blocks
    dim3 qc_grid((H_+127)/128, B_/NB);      // 4 x 128

    for (int t=0; t<T_; t++){
        // combined recurrent GEMM for BOTH GRUs (only depends on step t-1 states)
        gemm_all<<<gemm_grid,128>>>(h_all, WhhTq, WhhTp, bhh_q, bhh_p, Gh);

        // q GRU gate combine -> hq_t
        q_combine<<<qc_grid,128>>>(x + (size_t)t*XD_, WihTq, bih_q, Gh, h_all);

        // variational z step + planar flows
        const float* zprev = (t==0) ? zzero : (out_z + (size_t)(t-1)*ZD_);
        int zstride = (t==0) ? ZD_ : T_*ZD_;
        zstep_kernel<<<B_,32>>>(h_all, eps, zprev, zstride,
                                Wqm, bqm, Wqs, bqs, fw, fb,
                                out_z, out_mu, out_std, out_ld, t);

        // p GRU combine + reconstruction heads (hp stays in smem for recon)
        p_fused<<<B_/NB,256>>>(out_z + (size_t)t*ZD_, WihTp, bih_p, Gh, h_all,
                               Wpm, bpm, Wps, bps, out_rm, out_rs, t);
    }
}

// round 4
// speedup vs baseline: 2.3862x; 1.5668x over previous
#include <cuda_runtime.h>
#include <cuda_bf16.h>
#include <math.h>
#include <stdint.h>

#define B_   1024
#define T_   100
#define XD_  38
#define H_   500
#define ZD_  16
#define L_   3
#define G3H  1500
#define KP   512     // padded K (H_ -> 512)
#define NP   1536    // padded N (3H -> 1536)
#define M2   2048    // hq (1024) + hp (1024) stacked
#define NB   8
#define MT_  16      // M tiles of 128
#define NT_  12      // N tiles of 128
#define CH_  8       // K chunks of 64 bf16
#define CHB  16384   // bytes per (operand, chunk) image: 128 rows x 128B

// ----------------------------- scratch (static, no allocation) --------------
__device__ float g_h_all[M2*KP];               // fp32 recurrent state
__device__ float g_Gh[(size_t)M2*NP];          // raw recurrent matmul result (no bias)
__device__ uint8_t g_Abf[(size_t)MT_*2*CH_*CHB];    // state bf16 hi/lo, SW128 images
__device__ uint8_t g_Bbf[(size_t)2*NT_*2*CH_*CHB];  // weights bf16 hi/lo per GRU
__device__ float g_WihTq[XD_*G3H];
__device__ float g_WihTp[ZD_*G3H];
__device__ float g_uhat[L_*ZD_];
__device__ float g_zzero[B_*ZD_];

// ----------------------------- helpers ---------------------------------------
__device__ __forceinline__ float sigmoidf_(float x){ return 1.0f/(1.0f+expf(-x)); }
__device__ __forceinline__ float softplusf_(float x){ return (x>20.0f)? x : log1pf(expf(x)); }
__device__ __forceinline__ uint32_t swz128(uint32_t off){ return off ^ ((off>>3)&0x70); }

__device__ __forceinline__ size_t a_stage(int mt,int split,int ch){
    return (((size_t)mt*2 + split)*CH_ + ch)*CHB;
}
__device__ __forceinline__ size_t b_stage(int gru,int nt,int split,int ch){
    return ((((size_t)gru*NT_ + nt)*2 + split)*CH_ + ch)*CHB;
}
__device__ __forceinline__ void write_a_split(int m, int k, float v){
    int mt = m>>7, r = m&127, ch = k>>6, c = k&63;
    uint32_t sw = swz128((uint32_t)(r*128 + c*2));
    __nv_bfloat16 hi = __float2bfloat16(v);
    float rem = v - __bfloat162float(hi);
    __nv_bfloat16 lo = __float2bfloat16(rem);
    *(__nv_bfloat16*)(g_Abf + a_stage(mt,0,ch) + sw) = hi;
    *(__nv_bfloat16*)(g_Abf + a_stage(mt,1,ch) + sw) = lo;
}

__device__ __forceinline__ uint32_t smem_u32(const void* p){
    uint32_t a;
    asm("{ .reg .u64 t; cvta.to.shared.u64 t, %1; cvt.u32.u64 %0, t; }" : "=r"(a) : "l"(p));
    return a;
}
__device__ __forceinline__ void cp_async16(uint32_t dst, const void* src){
    asm volatile("cp.async.cg.shared.global [%0], [%1], 16;" :: "r"(dst), "l"(src));
}
__device__ __forceinline__ void cp_commit(){ asm volatile("cp.async.commit_group;" ::: "memory"); }
template<int N>
__device__ __forceinline__ void cp_wait(){ asm volatile("cp.async.wait_group %0;" :: "n"(N) : "memory"); }

__device__ __forceinline__ void ldsm_x4(uint32_t& r0, uint32_t& r1, uint32_t& r2, uint32_t& r3, uint32_t addr){
    asm volatile("ldmatrix.sync.aligned.m8n8.x4.shared.b16 {%0,%1,%2,%3}, [%4];"
                 : "=r"(r0), "=r"(r1), "=r"(r2), "=r"(r3) : "r"(addr));
}
__device__ __forceinline__ void mma_bf16(float* c, const uint32_t* a, const uint32_t* b){
    asm volatile("mma.sync.aligned.m16n8k16.row.col.f32.bf16.bf16.f32 "
                 "{%0,%1,%2,%3}, {%4,%5,%6,%7}, {%8,%9}, {%0,%1,%2,%3};"
                 : "+f"(c[0]), "+f"(c[1]), "+f"(c[2]), "+f"(c[3])
                 : "r"(a[0]), "r"(a[1]), "r"(a[2]), "r"(a[3]), "r"(b[0]), "r"(b[1]));
}

// ----------------------------- init ------------------------------------------
__global__ void init_kernel(float* __restrict__ out_ld){
    size_t i = (size_t)blockIdx.x*blockDim.x + threadIdx.x;
    size_t stride = (size_t)gridDim.x*blockDim.x;
    float4* h4 = (float4*)g_h_all;
    for (size_t k=i; k<(size_t)M2*KP/4; k+=stride) h4[k] = make_float4(0,0,0,0);
    uint4* a4 = (uint4*)g_Abf;
    for (size_t k=i; k<sizeof(g_Abf)/16; k+=stride) a4[k] = make_uint4(0,0,0,0);
    uint4* b4 = (uint4*)g_Bbf;
    for (size_t k=i; k<sizeof(g_Bbf)/16; k+=stride) b4[k] = make_uint4(0,0,0,0);
    for (size_t k=i; k<B_*ZD_; k+=stride) g_zzero[k]=0.f;
    for (size_t k=i; k<B_;     k+=stride) out_ld[k]=0.f;
}

// ----------------------------- weight staging ---------------------------------
__global__ void stage_whh(const float* __restrict__ W, int gru){
    int idx = blockIdx.x*blockDim.x + threadIdx.x;
    if (idx >= G3H*H_) return;
    int n = idx / H_, k = idx - n*H_;
    float v = W[idx];
    int nt = n>>7, r = n&127, ch = k>>6, c = k&63;
    uint32_t sw = swz128((uint32_t)(r*128 + c*2));
    __nv_bfloat16 hi = __float2bfloat16(v);
    float rem = v - __bfloat162float(hi);
    __nv_bfloat16 lo = __float2bfloat16(rem);
    *(__nv_bfloat16*)(g_Bbf + b_stage(gru,nt,0,ch) + sw) = hi;
    *(__nv_bfloat16*)(g_Bbf + b_stage(gru,nt,1,ch) + sw) = lo;
}

__global__ void transpose_wih(const float* __restrict__ W, float* __restrict__ WT, int C){
    int idx = blockIdx.x*blockDim.x + threadIdx.x;
    if (idx < G3H*C){
        int g = idx / C, d = idx - g*C;
        WT[(size_t)d*G3H + g] = W[idx];
    }
}

__global__ void uhat_kernel(const float* __restrict__ fu, const float* __restrict__ fw){
    int k = threadIdx.x;
    if (k < L_){
        float wu=0.f, ww=0.f;
        for (int j=0;j<ZD_;j++){ wu += fw[k*ZD_+j]*fu[k*ZD_+j]; ww += fw[k*ZD_+j]*fw[k*ZD_+j]; }
        float m = -1.0f + softplusf_(wu);
        float scale = (m - wu)/(ww + 1e-6f);
        for (int j=0;j<ZD_;j++) g_uhat[k*ZD_+j] = fu[k*ZD_+j] + scale*fw[k*ZD_+j];
    }
}

// ----------------------------- split-bf16 mma.sync GEMM ----------------------
// Gh[m][n] = sum_k h[m][k]*Whh[n][k], via hi*hi + hi*lo + lo*hi.
// CTA tile 128x128, 8 warps (2m x 4n), warp tile 64x32. K chunks of 64 bf16,
// cp.async double-buffered.
__global__ __launch_bounds__(256)
void gemm_tc(float* __restrict__ Gh){
    extern __shared__ uint8_t smem_raw[];
    uint8_t* tiles = (uint8_t*)(((uintptr_t)smem_raw + 1023) & ~(uintptr_t)1023);
    uint32_t sbase = smem_u32(tiles);

    int tid = threadIdx.x, wid = tid>>5, lane = tid&31;
    int nt = blockIdx.x, mt = blockIdx.y;
    int gru = mt>>3;
    int wm = wid & 1, wn = wid >> 1;

    float acc[4][4][4];
#pragma unroll
    for (int i=0;i<4;i++)
#pragma unroll
        for (int j=0;j<4;j++)
#pragma unroll
            for (int c=0;c<4;c++) acc[i][j][c]=0.f;

    int g = lane >> 3, l = lane & 7;
    // per-lane fragment address components (within a 16KB image)
    // A: row = wm*64 + mi*16 + (g&1)*8 + l ; kbyte = s*32 + (g>>1)*16
    // B: row = wn*32 + p*16 + (g>>1)*8 + l ; kbyte = s*32 + (g&1)*16
    int a_row = wm*64 + (g&1)*8 + l;
    int a_kb  = (g>>1)*16;
    int b_row = wn*32 + (g>>1)*8 + l;
    int b_kb  = (g&1)*16;

    // copy lambda: 4 images x 16KB per chunk, 16 x 16B per thread
    auto copy_chunk = [&](int ch, int buf){
        const uint8_t* srcs[4] = {
            g_Abf + a_stage(mt,0,ch), g_Abf + a_stage(mt,1,ch),
            g_Bbf + b_stage(gru,nt,0,ch), g_Bbf + b_stage(gru,nt,1,ch)
        };
        uint32_t dbase = sbase + buf*65536;
#pragma unroll
        for (int r=0;r<16;r++){
            int idx = r*256 + tid;
            int img = idx >> 10;
            int off = (idx & 1023)*16;
            cp_async16(dbase + img*16384 + off, srcs[img] + off);
        }
    };

    copy_chunk(0,0); cp_commit();

    for (int ch=0; ch<CH_; ch++){
        if (ch+1 < CH_){ copy_chunk(ch+1,(ch+1)&1); cp_commit(); cp_wait<1>(); }
        else cp_wait<0>();
        __syncthreads();

        uint32_t Ahi_b = sbase + (ch&1)*65536;
        uint32_t Alo_b = Ahi_b + 16384;
        uint32_t Bhi_b = Ahi_b + 32768;
        uint32_t Blo_b = Ahi_b + 49152;

#pragma unroll
        for (int s=0; s<4; s++){
            uint32_t Ah[4][4], Al[4][4], Bh[4][2], Bl[4][2];
            uint32_t a_off = swz128((uint32_t)(a_row*128 + s*32 + a_kb));
            uint32_t b_off = swz128((uint32_t)(b_row*128 + s*32 + b_kb));
#pragma unroll
            for (int mi=0; mi<4; mi++){
                uint32_t ao = a_off + mi*16*128;     // +16 rows: bits>=7 unaffected by swizzle XOR target bits[6:4]? (16*128=2048, bits 11+) safe
                ldsm_x4(Ah[mi][0],Ah[mi][1],Ah[mi][2],Ah[mi][3], Ahi_b + ao);
                ldsm_x4(Al[mi][0],Al[mi][1],Al[mi][2],Al[mi][3], Alo_b + ao);
            }
#pragma unroll
            for (int p=0; p<2; p++){
                uint32_t bo = b_off + p*16*128;
                uint32_t r0,r1,r2,r3;
                ldsm_x4(r0,r1,r2,r3, Bhi_b + bo);
                Bh[2*p][0]=r0; Bh[2*p][1]=r1; Bh[2*p+1][0]=r2; Bh[2*p+1][1]=r3;
                ldsm_x4(r0,r1,r2,r3, Blo_b + bo);
                Bl[2*p][0]=r0; Bl[2*p][1]=r1; Bl[2*p+1][0]=r2; Bl[2*p+1][1]=r3;
            }
#pragma unroll
            for (int mi=0; mi<4; mi++)
#pragma unroll
                for (int ni=0; ni<4; ni++){
                    mma_bf16(acc[mi][ni], Ah[mi], Bh[ni]);
                    mma_bf16(acc[mi][ni], Ah[mi], Bl[ni]);
                    mma_bf16(acc[mi][ni], Al[mi], Bh[ni]);
                }
        }
        __syncthreads();
    }

    // epilogue: write Gh
    int mbase = mt*128 + wm*64;
    int nbase = nt*128 + wn*32;
    int rr = lane>>2, cc = (lane&3)*2;
#pragma unroll
    for (int mi=0; mi<4; mi++){
#pragma unroll
        for (int ni=0; ni<4; ni++){
            int m = mbase + mi*16 + rr;
            int n = nbase + ni*8 + cc;
            *(float2*)&Gh[(size_t)m*NP + n]     = make_float2(acc[mi][ni][0], acc[mi][ni][1]);
            *(float2*)&Gh[(size_t)(m+8)*NP + n] = make_float2(acc[mi][ni][2], acc[mi][ni][3]);
        }
    }
}

// ----------------------------- q GRU combine ---------------------------------
__global__ __launch_bounds__(128)
void q_combine(const float* __restrict__ xbase,
               const float* __restrict__ WihT, const float* __restrict__ bih,
               const float* __restrict__ bhh,
               const float* __restrict__ Gh,
               float* __restrict__ h_all){
    __shared__ float xs[NB][XD_+2];
    int b0 = blockIdx.y * NB;
    int j  = blockIdx.x*blockDim.x + threadIdx.x;
    for (int idx=threadIdx.x; idx<NB*XD_; idx+=blockDim.x){
        int r = idx / XD_, d = idx - r*XD_;
        xs[r][d] = xbase[(size_t)(b0+r)*(T_*XD_) + d];
    }
    __syncthreads();
    if (j >= H_) return;

    float ar[NB], az[NB], an[NB];
#pragma unroll
    for (int r=0;r<NB;r++){ ar[r]=0.f; az[r]=0.f; an[r]=0.f; }
    for (int d=0; d<XD_; d++){
        const float* wrow = WihT + (size_t)d*G3H;
        float w0 = wrow[j], w1 = wrow[H_+j], w2 = wrow[2*H_+j];
#pragma unroll
        for (int r=0;r<NB;r++){
            float xv = xs[r][d];
            ar[r] = fmaf(xv, w0, ar[r]);
            az[r] = fmaf(xv, w1, az[r]);
            an[r] = fmaf(xv, w2, an[r]);
        }
    }
    float bR = bih[j] + bhh[j], bZ = bih[H_+j] + bhh[H_+j];
    float bN = bih[2*H_+j], bhN = bhh[2*H_+j];
#pragma unroll
    for (int r=0;r<NB;r++){
        const float* gh = Gh + (size_t)(b0+r)*NP;
        float rg = sigmoidf_(ar[r] + bR + gh[j]);
        float zz = sigmoidf_(az[r] + bZ + gh[H_+j]);
        float nn = tanhf    (an[r] + bN + rg*(gh[2*H_+j] + bhN));
        size_t hi = (size_t)(b0+r)*KP + j;
        float hv = (1.f - zz)*nn + zz*h_all[hi];
        h_all[hi] = hv;
        write_a_split(b0+r, j, hv);
    }
}

// ----------------------------- z step (mu/std + planar flows) ----------------
__global__ __launch_bounds__(32)
void zstep_kernel(const float* __restrict__ h_all,
                  const float* __restrict__ eps,
                  const float* __restrict__ zprev, int zstride,
                  const float* __restrict__ Wqm, const float* __restrict__ bqm,
                  const float* __restrict__ Wqs, const float* __restrict__ bqs,
                  const float* __restrict__ fw, const float* __restrict__ fb,
                  float* __restrict__ out_z, float* __restrict__ out_mu,
                  float* __restrict__ out_std, float* __restrict__ out_ld, int t){
    __shared__ float comb[H_+ZD_];
    __shared__ float smu[ZD_], sstd[ZD_], zsh[ZD_];
    int b = blockIdx.x, lane = threadIdx.x;
    for (int i=lane; i<H_; i+=32) comb[i] = h_all[(size_t)b*KP + i];
    if (lane < ZD_) comb[H_+lane] = zprev[(size_t)b*zstride + lane];
    __syncwarp();

    int j = lane & 15;
    const float* W = (lane < 16 ? Wqm : Wqs) + (size_t)j*(H_+ZD_);
    float acc = 0.f;
    for (int i=0;i<H_+ZD_;i++) acc = fmaf(comb[i], W[i], acc);
    size_t oidx = ((size_t)b*T_ + t)*ZD_ + j;
    if (lane < 16){ float mu = acc + bqm[j]; smu[j] = mu; out_mu[oidx] = mu; }
    else          { float s  = softplusf_(acc + bqs[j]) + 1e-4f; sstd[j] = s; out_std[oidx] = s; }
    __syncwarp();

    if (lane < ZD_)
        zsh[lane] = smu[lane] + eps[((size_t)b*T_ + t)*ZD_ + lane]*sstd[lane];
    __syncwarp();

    if (lane == 0){
        float ld = 0.f;
#pragma unroll
        for (int k=0;k<L_;k++){
            float dot = 0.f;
            for (int i=0;i<ZD_;i++) dot = fmaf(zsh[i], fw[k*ZD_+i], dot);
            float hh = tanhf(dot + fb[k]);
            float psiu = 0.f;
            for (int i=0;i<ZD_;i++){
                zsh[i] += g_uhat[k*ZD_+i]*hh;
                psiu = fmaf((1.f - hh*hh)*fw[k*ZD_+i], g_uhat[k*ZD_+i], psiu);
            }
            ld += logf(fabsf(1.f + psiu) + 1e-6f);
        }
        out_ld[b] += ld;
    }
    __syncwarp();
    if (lane < ZD_) out_z[((size_t)b*T_ + t)*ZD_ + lane] = zsh[lane];
}

// ----------------------------- p GRU combine + reconstruction ----------------
__global__ __launch_bounds__(256)
void p_fused(const float* __restrict__ z_t,
             const float* __restrict__ WihT, const float* __restrict__ bih,
             const float* __restrict__ bhh,
             const float* __restrict__ Gh,
             float* __restrict__ h_all,
             const float* __restrict__ Wpm, const float* __restrict__ bpm,
             const float* __restrict__ Wps, const float* __restrict__ bps,
             float* __restrict__ out_mu, float* __restrict__ out_std, int t){
    __shared__ float zs[NB][ZD_];
    __shared__ float hs[NB][H_];
    int b0 = blockIdx.x * NB;
    int tid = threadIdx.x;
    if (tid < NB*ZD_){
        int r = tid >> 4, d = tid & 15;
        zs[r][d] = z_t[(size_t)(b0+r)*(T_*ZD_) + d];
    }
    __syncthreads();

    for (int j = tid; j < H_; j += 256){
        float ar[NB], az[NB], an[NB];
#pragma unroll
        for (int r=0;r<NB;r++){ ar[r]=0.f; az[r]=0.f; an[r]=0.f; }
#pragma unroll
        for (int d=0; d<ZD_; d++){
            const float* wrow = WihT + (size_t)d*G3H;
            float w0 = wrow[j], w1 = wrow[H_+j], w2 = wrow[2*H_+j];
#pragma unroll
            for (int r=0;r<NB;r++){
                float zv = zs[r][d];
                ar[r] = fmaf(zv, w0, ar[r]);
                az[r] = fmaf(zv, w1, az[r]);
                an[r] = fmaf(zv, w2, an[r]);
            }
        }
        float bR = bih[j] + bhh[j], bZ = bih[H_+j] + bhh[H_+j];
        float bN = bih[2*H_+j], bhN = bhh[2*H_+j];
#pragma unroll
        for (int r=0;r<NB;r++){
            const float* gh = Gh + (size_t)(1024 + b0 + r)*NP;
            float rg = sigmoidf_(ar[r] + bR + gh[j]);
            float zz = sigmoidf_(az[r] + bZ + gh[H_+j]);
            float nn = tanhf    (an[r] + bN + rg*(gh[2*H_+j] + bhN));
            size_t hi = (size_t)(1024 + b0 + r)*KP + j;
            float hv = (1.f - zz)*nn + zz*h_all[hi];
            h_all[hi] = hv;
            hs[r][j]  = hv;
            write_a_split(1024 + b0 + r, j, hv);
        }
    }
    __syncthreads();

    int rg2 = tid >> 7;
    int o  = tid & 127;
    if (o < XD_){
        const float* w = Wpm + (size_t)o*H_;
        float a0=0.f,a1=0.f,a2=0.f,a3=0.f;
        for (int i=0;i<H_;i++){
            float wv = w[i];
            a0 = fmaf(hs[rg2*4+0][i], wv, a0);
            a1 = fmaf(hs[rg2*4+1][i], wv, a1);
            a2 = fmaf(hs[rg2*4+2][i], wv, a2);
            a3 = fmaf(hs[rg2*4+3][i], wv, a3);
        }
        float bb = bpm[o];
        out_mu[((size_t)(b0+rg2*4+0)*T_+t)*XD_+o] = a0+bb;
        out_mu[((size_t)(b0+rg2*4+1)*T_+t)*XD_+o] = a1+bb;
        out_mu[((size_t)(b0+rg2*4+2)*T_+t)*XD_+o] = a2+bb;
        out_mu[((size_t)(b0+rg2*4+3)*T_+t)*XD_+o] = a3+bb;
    } else if (o >= 64 && o < 64+XD_){
        int d = o - 64;
        const float* w = Wps + (size_t)d*H_;
        float a0=0.f,a1=0.f,a2=0.f,a3=0.f;
        for (int i=0;i<H_;i++){
            float wv = w[i];
            a0 = fmaf(hs[rg2*4+0][i], wv, a0);
            a1 = fmaf(hs[rg2*4+1][i], wv, a1);
            a2 = fmaf(hs[rg2*4+2][i], wv, a2);
            a3 = fmaf(hs[rg2*4+3][i], wv, a3);
        }
        float bb = bps[d];
        out_std[((size_t)(b0+rg2*4+0)*T_+t)*XD_+d] = softplusf_(a0+bb)+1e-4f;
        out_std[((size_t)(b0+rg2*4+1)*T_+t)*XD_+d] = softplusf_(a1+bb)+1e-4f;
        out_std[((size_t)(b0+rg2*4+2)*T_+t)*XD_+d] = softplusf_(a2+bb)+1e-4f;
        out_std[((size_t)(b0+rg2*4+3)*T_+t)*XD_+d] = softplusf_(a3+bb)+1e-4f;
    }
}

// ----------------------------- launcher --------------------------------------
extern "C" void kernel_launch(void* const* d_in, const int* in_sizes, int n_in,
                              void* d_out, int out_size){
    const float* x     = (const float*)d_in[0];
    const float* eps   = (const float*)d_in[1];
    const float* Wih_q = (const float*)d_in[2];
    const float* Whh_q = (const float*)d_in[3];
    const float* bih_q = (const float*)d_in[4];
    const float* bhh_q = (const float*)d_in[5];
    const float* Wqm   = (const float*)d_in[6];
    const float* bqm   = (const float*)d_in[7];
    const float* Wqs   = (const float*)d_in[8];
    const float* bqs   = (const float*)d_in[9];
    const float* Wih_p = (const float*)d_in[10];
    const float* Whh_p = (const float*)d_in[11];
    const float* bih_p = (const float*)d_in[12];
    const float* bhh_p = (const float*)d_in[13];
    const float* Wpm   = (const float*)d_in[14];
    const float* bpm   = (const float*)d_in[15];
    const float* Wps   = (const float*)d_in[16];
    const float* bps   = (const float*)d_in[17];
    const float* fu    = (const float*)d_in[18];
    const float* fw    = (const float*)d_in[19];
    const float* fb    = (const float*)d_in[20];

    float* out = (float*)d_out;
    float* out_rm  = out;
    float* out_rs  = out_rm  + (size_t)B_*T_*XD_;
    float* out_z   = out_rs  + (size_t)B_*T_*XD_;
    float* out_mu  = out_z   + (size_t)B_*T_*ZD_;
    float* out_std = out_mu  + (size_t)B_*T_*ZD_;
    float* out_ld  = out_std + (size_t)B_*T_*ZD_;

    float *h_all,*Gh,*WihTq,*WihTp,*zzero;
    cudaGetSymbolAddress((void**)&h_all, g_h_all);
    cudaGetSymbolAddress((void**)&Gh,    g_Gh);
    cudaGetSymbolAddress((void**)&WihTq, g_WihTq);
    cudaGetSymbolAddress((void**)&WihTp, g_WihTp);
    cudaGetSymbolAddress((void**)&zzero, g_zzero);

    cudaFuncSetAttribute(gemm_tc, cudaFuncAttributeMaxDynamicSharedMemorySize, 132096);

    init_kernel<<<1024,256>>>(out_ld);
    {
        int n = G3H*H_;
        stage_whh<<<(n+255)/256,256>>>(Whh_q, 0);
        stage_whh<<<(n+255)/256,256>>>(Whh_p, 1);
        int nq = G3H*XD_;
        transpose_wih<<<(nq+255)/256,256>>>(Wih_q, WihTq, XD_);
        int np = G3H*ZD_;
        transpose_wih<<<(np+255)/256,256>>>(Wih_p, WihTp, ZD_);
    }
    uhat_kernel<<<1,32>>>(fu, fw);

    dim3 gemm_grid(NT_, MT_);               // 12 x 16 = 192 CTAs
    dim3 qc_grid((H_+127)/128, B_/NB);

    for (int t=0; t<T_; t++){
        // combined recurrent GEMM for BOTH GRUs (mma.sync bf16-split)
        gemm_tc<<<gemm_grid,256,132096>>>(Gh);

        // q GRU gate combine -> hq_t (+ bf16 split staging for next GEMM)
        q_combine<<<qc_grid,128>>>(x + (size_t)t*XD_, WihTq, bih_q, bhh_q, Gh, h_all);

        // variational z step + planar flows
        const float* zprev = (t==0) ? zzero : (out_z + (size_t)(t-1)*ZD_);
        int zstride = (t==0) ? ZD_ : T_*ZD_;
        zstep_kernel<<<B_,32>>>(h_all, eps, zprev, zstride,
                                Wqm, bqm, Wqs, bqs, fw, fb,
                                out_z, out_mu, out_std, out_ld, t);

        // p GRU combine + reconstruction heads
        p_fused<<<B_/NB,256>>>(out_z + (size_t)t*ZD_, WihTp, bih_p, bhh_p, Gh, h_all,
                               Wpm, bpm, Wps, bps, out_rm, out_rs, t);
    }
}